// round 9
// baseline (speedup 1.0000x reference)
#include <cuda_runtime.h>
#include <cuda_bf16.h>

#define B 512
#define T 512
#define C 96

__device__ float g_den[B];
__device__ float g_num[B];
__device__ int g_tag_any;      // any odd 32-bit word nonzero => tags are int32
__device__ int g_mask_byte;    // any mask word > 1 => mask stored as bytes
__device__ int g_not_ones_b;   // (byte mask) some word != 0x01010101
__device__ int g_not_ones_w;   // (int32 mask) some word != 1

__device__ __forceinline__ void unpack2(unsigned long long v, float& lo, float& hi) {
    asm("mov.b64 {%0, %1}, %2;" : "=f"(lo), "=f"(hi) : "l"(v));
}
__device__ __forceinline__ unsigned long long pack2(float lo, float hi) {
    unsigned long long r;
    asm("mov.b64 %0, {%1, %2};" : "=l"(r) : "f"(lo), "f"(hi));
    return r;
}
__device__ __forceinline__ unsigned long long ffma2(unsigned long long a,
                                                    unsigned long long b,
                                                    unsigned long long c) {
    unsigned long long d;
    asm("fma.rn.f32x2 %0, %1, %2, %3;" : "=l"(d) : "l"(a), "l"(b), "l"(c));
    return d;
}
__device__ __forceinline__ unsigned long long fadd2(unsigned long long a,
                                                    unsigned long long b) {
    unsigned long long d;
    asm("add.rn.f32x2 %0, %1, %2;" : "=l"(d) : "l"(a), "l"(b));
    return d;
}
__device__ __forceinline__ float frcp_fast(float x) {
    float r;
    asm("rcp.approx.f32 %0, %1;" : "=f"(r) : "f"(x));
    return r;
}
__device__ __forceinline__ void bar_sub(int id) {
    asm volatile("bar.sync %0, %1;" :: "r"(id), "r"(96) : "memory");
}

// ---------------------------------------------------------------------------
// Detection kernels.
__global__ void crf_init_kernel()
{
    g_tag_any = 0; g_mask_byte = 0; g_not_ones_b = 0; g_not_ones_w = 0;
}

__global__ void __launch_bounds__(256) crf_detect_a_kernel(
    const int* __restrict__ t32, const unsigned int* __restrict__ mw)
{
    const int gt = blockIdx.x * 256 + threadIdx.x;
    int ta = 0, mb = 0, nb = 0, nw = 0;
    for (int i = gt; i < 512; i += 64 * 256)
        if (t32[i * 2 + 1] != 0) ta = 1;
    for (int i = gt; i < 65536; i += 64 * 256) {   // first 256 KB: full byte-mask span
        const unsigned int v = mw[i];
        if (v > 1u) mb = 1;
        if (v != 0x01010101u) nb = 1;
        if (v != 1u) nw = 1;
    }
    if (ta) atomicOr(&g_tag_any, 1);
    if (mb) atomicOr(&g_mask_byte, 1);
    if (nb) atomicOr(&g_not_ones_b, 1);
    if (nw) atomicOr(&g_not_ones_w, 1);
}

__global__ void __launch_bounds__(256) crf_detect_b_kernel(
    const unsigned int* __restrict__ mw)
{
    if (g_mask_byte) return;                       // byte mask: buffer is only 256 KB
    const int gt = blockIdx.x * 256 + threadIdx.x;
    int nw = 0;
    for (int i = 65536 + gt; i < 262144; i += 64 * 256)
        if (mw[i] != 1u) nw = 1;
    if (nw) atomicOr(&g_not_ones_w, 1);
}

// ---------------------------------------------------------------------------
// FAST forward (mask all ones): linear-space recurrence, register-blocked.
//   u_t[j] = (sum_i u_{t-1}[i] * E[i][j]) * exp(emit_t[j]) / c_t,  c_t = u_{t-1}[0]
// CTA = 384 threads = FOUR independent 96-thread subs (one chain each) with
// named barriers. The 4-sub layout makes wid%4 SMSP assignment PERFECTLY
// balanced: sub0->{0,1,2}, sub1->{3,0,1}, sub2->{2,3,0}, sub3->{1,2,3} => each
// SMSP hosts exactly 3 warps, each from a DIFFERENT sub (decorrelated phases).
// Per sub: thread (j = ts>>1, h = ts&1) computes TWO states {j, j+48}, half h
// of each dot: every LDS.128 of u feeds 4 FFMA2. After the shfl-combine, lane
// h finishes state j+48h. log(c_t) deferred to a post-loop reduction.
__global__ void __launch_bounds__(384, 1) crf_forward_fast_kernel(
    const float* __restrict__ emissions,
    const float* __restrict__ start_t,
    const float* __restrict__ end_t,
    const float* __restrict__ trans)
{
    const int allones = g_mask_byte ? !g_not_ones_b : !g_not_ones_w;
    if (!allones) return;

    const int tid = threadIdx.x;
    const int sub = tid / 96;          // 0..3
    const int ts  = tid - sub * 96;    // 0..95
    const int j   = ts >> 1;           // 0..47
    const int h   = ts & 1;            // dot half / owned-state selector
    const int jh  = j + 48 * h;        // owned state
    const int b   = blockIdx.x * 4 + sub;

    __shared__ __align__(16) float sh_u[4][2][C];   // [sub][buf][state]
    __shared__ float sh_hist[4][T];
    __shared__ float sh_re[4][3];
    __shared__ float sh_rl[4][3];

    // E rows [48h, 48h+48) of columns j and j+48, packed f32x2 (48 u64 regs)
    unsigned long long EJ[24], EK[24];
    {
        const float* tbJ = trans + (size_t)(48 * h) * C + j;
        const float* tbK = tbJ + 48;
#pragma unroll
        for (int k = 0; k < 24; k++) {
            EJ[k] = pack2(__expf(tbJ[(2 * k) * C]), __expf(tbJ[(2 * k + 1) * C]));
            EK[k] = pack2(__expf(tbK[(2 * k) * C]), __expf(tbK[(2 * k + 1) * C]));
        }
    }

    const float* em0 = emissions + (size_t)b * T * C;     // chain base
    const float* emS = em0 + jh;                          // owned state stream
    const float  a00 = start_t[0] + em0[0];

    sh_u[sub][0][ts] = __expf(start_t[ts] + em0[ts] - a00);   // u0 (u0[0] = 1)

    float ee1 = __expf(emS[C]);             // exp(emit) for t=1, owned state
    float er2 = emS[2 * (size_t)C];         // raw emit for t=2
    const float* em_pre = emS + 3 * (size_t)C;

    bar_sub(sub + 1);

    int buf = 0;
#pragma unroll 2
    for (int t = 1; t < T; t++) {
        const float c   = sh_u[sub][buf][0];    // broadcast LDS.32
        const float inv = frcp_fast(c);         // overlaps the dot
        if (ts == 0) sh_hist[sub][t] = c;

        // half-dots for BOTH owned states: 12 LDS.128 -> 48 FFMA2
        const ulonglong2* p2 = (const ulonglong2*)(sh_u[sub][buf] + 48 * h);
        unsigned long long aJ0 = 0ull, aJ1 = 0ull, aK0 = 0ull, aK1 = 0ull;
#pragma unroll
        for (int k = 0; k < 12; k++) {
            const ulonglong2 v = p2[k];
            aJ0 = ffma2(v.x, EJ[2 * k + 0], aJ0);
            aK0 = ffma2(v.x, EK[2 * k + 0], aK0);
            aJ1 = ffma2(v.y, EJ[2 * k + 1], aJ1);
            aK1 = ffma2(v.y, EK[2 * k + 1], aK1);
        }
        float jl, jhf, kl, khf;
        unpack2(fadd2(aJ0, aJ1), jl, jhf);
        unpack2(fadd2(aK0, aK1), kl, khf);
        float dJ = jl + jhf;                              // state j, half h
        float dK = kl + khf;                              // state j+48, half h
        dJ += __shfl_xor_sync(0xffffffffu, dJ, 1);        // full dots (both lanes)
        dK += __shfl_xor_sync(0xffffffffu, dK, 1);

        const float dot_self = h ? dK : dJ;
        sh_u[sub][buf ^ 1][jh] = dot_self * (ee1 * inv);

        // rotate owned-state emission prefetch (off critical path)
        ee1 = __expf(er2);
        if (t + 2 < T) er2 = *em_pre;
        em_pre += C;

        buf ^= 1;
        bar_sub(sub + 1);
    }

    // log_den[b] = a00 + sum_t log(c_t) + log( sum_j u_T[j] * exp(end[j]) )
    float pe = sh_u[sub][buf][jh] * __expf(end_t[jh]);    // each state once
    float pl = 0.0f;
    for (int tt = 1 + ts; tt < T; tt += 96) pl += __logf(sh_hist[sub][tt]);
#pragma unroll
    for (int off = 16; off > 0; off >>= 1) {
        pe += __shfl_xor_sync(0xffffffffu, pe, off);
        pl += __shfl_xor_sync(0xffffffffu, pl, off);
    }
    const int w    = ts >> 5;
    const int lane = ts & 31;
    if (lane == 0) { sh_re[sub][w] = pe; sh_rl[sub][w] = pl; }
    bar_sub(sub + 1);
    if (ts == 0) {
        const float te = sh_re[sub][0] + sh_re[sub][1] + sh_re[sub][2];
        const float tl = sh_rl[sub][0] + sh_rl[sub][1] + sh_rl[sub][2];
        g_den[b] = a00 + tl + __logf(te);
    }
}

// ---------------------------------------------------------------------------
// FALLBACK forward (general mask): log-space, shifted lse.
__global__ void __launch_bounds__(384, 1) crf_forward_gen_kernel(
    const float* __restrict__ emissions,
    const unsigned char* __restrict__ mask,
    const float* __restrict__ start_t,
    const float* __restrict__ end_t,
    const float* __restrict__ trans)
{
    const int allones = g_mask_byte ? !g_not_ones_b : !g_not_ones_w;
    if (allones) return;

    const int tid  = threadIdx.x;
    const int sub  = tid / C;
    const int j    = tid - sub * C;
    const int wsub = j >> 5;
    const int lane = j & 31;
    const int b    = blockIdx.x * 4 + sub;
    const int ms   = g_mask_byte ? 1 : 4;

    __shared__ __align__(16) float sh_p[2][4][C];
    __shared__ float sh_m[2][4];
    __shared__ float sh_r[4][4];

    unsigned long long E2[C / 2];
    {
        const float* tb = trans + j;
#pragma unroll
        for (int k = 0; k < C / 2; k++)
            E2[k] = pack2(__expf(tb[(2 * k) * C]), __expf(tb[(2 * k + 1) * C]));
    }

    const float* em = emissions + (size_t)b * T * C + j;
    const unsigned char* mk = mask + (size_t)b * T * ms;

    float alpha = start_t[j] + em[0];
    float m = start_t[0] + emissions[(size_t)b * T * C];

    float e1 = em[C];
    float e2 = em[2 * (size_t)C];
    unsigned char k1 = mk[1 * ms];
    unsigned char k2 = mk[2 * ms];

    int buf = 0;
    for (int t = 1; t < T; t++, buf ^= 1) {
        sh_p[buf][sub][j] = __expf(alpha - m);
        if (j == 0) sh_m[buf][sub] = alpha;
        __syncthreads();

        const ulonglong2* p2 = (const ulonglong2*)sh_p[buf][sub];
        unsigned long long a0 = 0ull, a1 = 0ull;
#pragma unroll
        for (int i = 0; i < C / 4; i++) {
            const ulonglong2 v = p2[i];
            a0 = ffma2(v.x, E2[2 * i + 0], a0);
            a1 = ffma2(v.y, E2[2 * i + 1], a1);
        }
        float lo, hi;
        unpack2(fadd2(a0, a1), lo, hi);
        const float acc = lo + hi;

        const float e_cur = e1;
        const unsigned char mc = k1;
        e1 = e2; k1 = k2;
        if (t + 2 < T) { e2 = em[(size_t)(t + 2) * C]; k2 = mk[(size_t)(t + 2) * ms]; }

        const float na = e_cur + m + __logf(acc);
        alpha = mc ? na : alpha;
        m = sh_m[buf][sub];
    }

    const float v = alpha + end_t[j];
    float wm = v;
    wm = fmaxf(wm, __shfl_xor_sync(0xffffffffu, wm, 16));
    wm = fmaxf(wm, __shfl_xor_sync(0xffffffffu, wm, 8));
    wm = fmaxf(wm, __shfl_xor_sync(0xffffffffu, wm, 4));
    wm = fmaxf(wm, __shfl_xor_sync(0xffffffffu, wm, 2));
    wm = fmaxf(wm, __shfl_xor_sync(0xffffffffu, wm, 1));
    if (lane == 0) sh_r[sub][wsub] = wm;
    __syncthreads();
    const float mf = fmaxf(fmaxf(sh_r[sub][0], sh_r[sub][1]), sh_r[sub][2]);
    __syncthreads();

    float pv = __expf(v - mf);
    pv += __shfl_xor_sync(0xffffffffu, pv, 16);
    pv += __shfl_xor_sync(0xffffffffu, pv, 8);
    pv += __shfl_xor_sync(0xffffffffu, pv, 4);
    pv += __shfl_xor_sync(0xffffffffu, pv, 2);
    pv += __shfl_xor_sync(0xffffffffu, pv, 1);
    if (lane == 0) sh_r[sub][wsub] = pv;
    __syncthreads();
    if (j == 0)
        g_den[b] = mf + __logf(sh_r[sub][0] + sh_r[sub][1] + sh_r[sub][2]);
}

// ---------------------------------------------------------------------------
// Numerator (path score): one CTA per batch element.
__global__ void __launch_bounds__(128) crf_score_kernel(
    const float* __restrict__ emissions,
    const void* __restrict__ tags_raw,
    const unsigned char* __restrict__ mask,
    const float* __restrict__ start_t,
    const float* __restrict__ end_t,
    const float* __restrict__ trans)
{
    const int b = blockIdx.x;
    const int tid = threadIdx.x;
    const int is32 = g_tag_any;
    const int ms = g_mask_byte ? 1 : 4;

    const int* tg32 = (const int*)tags_raw + (size_t)b * T;
    const long long* tg64 = (const long long*)tags_raw + (size_t)b * T;
    const unsigned char* mk = mask + (size_t)b * T * ms;
    const float* eb = emissions + (size_t)b * T * C;

    float sacc = 0.f;
    int len = 0;
    for (int t = tid; t < T; t += 128) {
        const int mt = mk[(size_t)t * ms] ? 1 : 0;
        len += mt;
        if (t >= 1 && mt) {
            const int ct = is32 ? tg32[t] : (int)tg64[t];
            const int pt = is32 ? tg32[t - 1] : (int)tg64[t - 1];
            sacc += eb[(size_t)t * C + ct] + trans[pt * C + ct];
        }
    }

    __shared__ float rs[128];
    __shared__ int   rl[128];
    rs[tid] = sacc;
    rl[tid] = len;
    __syncthreads();
#pragma unroll
    for (int off = 64; off > 0; off >>= 1) {
        if (tid < off) { rs[tid] += rs[tid + off]; rl[tid] += rl[tid + off]; }
        __syncthreads();
    }
    if (tid == 0) {
        const int t0    = is32 ? tg32[0] : (int)tg64[0];
        const int tlast = is32 ? tg32[rl[0] - 1] : (int)tg64[rl[0] - 1];
        g_num[b] = rs[0] + start_t[t0] + eb[t0] + end_t[tlast];
    }
}

// Mean over batch of (log_den - log_num).
__global__ void __launch_bounds__(512) crf_final_kernel(float* __restrict__ out)
{
    const int tid = threadIdx.x;
    __shared__ float r[512];
    r[tid] = g_den[tid] - g_num[tid];
    __syncthreads();
#pragma unroll
    for (int off = 256; off > 0; off >>= 1) {
        if (tid < off) r[tid] += r[tid + off];
        __syncthreads();
    }
    if (tid == 0) out[0] = r[0] * (1.0f / (float)B);
}

extern "C" void kernel_launch(void* const* d_in, const int* in_sizes, int n_in,
                              void* d_out, int out_size)
{
    const float*         emissions = (const float*)d_in[0];
    const void*          tags      = d_in[1];
    const unsigned char* mask      = (const unsigned char*)d_in[2];
    const float*         start_t   = (const float*)d_in[3];
    const float*         end_t     = (const float*)d_in[4];
    const float*         trans     = (const float*)d_in[5];
    float* out = (float*)d_out;

    crf_init_kernel<<<1, 1>>>();
    crf_detect_a_kernel<<<64, 256>>>((const int*)tags, (const unsigned int*)mask);
    crf_detect_b_kernel<<<64, 256>>>((const unsigned int*)mask);
    crf_forward_fast_kernel<<<B / 4, 384>>>(emissions, start_t, end_t, trans);
    crf_forward_gen_kernel<<<B / 4, 384>>>(emissions, mask, start_t, end_t, trans);
    crf_score_kernel<<<B, 128>>>(emissions, tags, mask, start_t, end_t, trans);
    crf_final_kernel<<<1, 512>>>(out);
}

// round 10
// speedup vs baseline: 1.0302x; 1.0302x over previous
#include <cuda_runtime.h>
#include <cuda_bf16.h>

#define B 512
#define T 512
#define C 96

__device__ float g_den[B];
__device__ float g_num[B];
__device__ int g_tag_any;      // any odd 32-bit word nonzero => tags are int32
__device__ int g_mask_byte;    // any mask word > 1 => mask stored as bytes
__device__ int g_not_ones_b;   // (byte mask) some word != 0x01010101
__device__ int g_not_ones_w;   // (int32 mask) some word != 1

__device__ __forceinline__ void unpack2(unsigned long long v, float& lo, float& hi) {
    asm("mov.b64 {%0, %1}, %2;" : "=f"(lo), "=f"(hi) : "l"(v));
}
__device__ __forceinline__ unsigned long long pack2(float lo, float hi) {
    unsigned long long r;
    asm("mov.b64 %0, {%1, %2};" : "=l"(r) : "f"(lo), "f"(hi));
    return r;
}
__device__ __forceinline__ unsigned long long ffma2(unsigned long long a,
                                                    unsigned long long b,
                                                    unsigned long long c) {
    unsigned long long d;
    asm("fma.rn.f32x2 %0, %1, %2, %3;" : "=l"(d) : "l"(a), "l"(b), "l"(c));
    return d;
}
__device__ __forceinline__ unsigned long long fadd2(unsigned long long a,
                                                    unsigned long long b) {
    unsigned long long d;
    asm("add.rn.f32x2 %0, %1, %2;" : "=l"(d) : "l"(a), "l"(b));
    return d;
}
__device__ __forceinline__ float frcp_fast(float x) {
    float r;
    asm("rcp.approx.f32 %0, %1;" : "=f"(r) : "f"(x));
    return r;
}
__device__ __forceinline__ void bar_sub(int id) {
    asm volatile("bar.sync %0, %1;" :: "r"(id), "r"(96) : "memory");
}

// ---------------------------------------------------------------------------
// Detection kernels.
__global__ void crf_init_kernel()
{
    g_tag_any = 0; g_mask_byte = 0; g_not_ones_b = 0; g_not_ones_w = 0;
}

__global__ void __launch_bounds__(256) crf_detect_a_kernel(
    const int* __restrict__ t32, const unsigned int* __restrict__ mw)
{
    const int gt = blockIdx.x * 256 + threadIdx.x;
    int ta = 0, mb = 0, nb = 0, nw = 0;
    for (int i = gt; i < 512; i += 64 * 256)
        if (t32[i * 2 + 1] != 0) ta = 1;
    for (int i = gt; i < 65536; i += 64 * 256) {   // first 256 KB: full byte-mask span
        const unsigned int v = mw[i];
        if (v > 1u) mb = 1;
        if (v != 0x01010101u) nb = 1;
        if (v != 1u) nw = 1;
    }
    if (ta) atomicOr(&g_tag_any, 1);
    if (mb) atomicOr(&g_mask_byte, 1);
    if (nb) atomicOr(&g_not_ones_b, 1);
    if (nw) atomicOr(&g_not_ones_w, 1);
}

__global__ void __launch_bounds__(256) crf_detect_b_kernel(
    const unsigned int* __restrict__ mw)
{
    if (g_mask_byte) return;                       // byte mask: buffer is only 256 KB
    const int gt = blockIdx.x * 256 + threadIdx.x;
    int nw = 0;
    for (int i = 65536 + gt; i < 262144; i += 64 * 256)
        if (mw[i] != 1u) nw = 1;
    if (nw) atomicOr(&g_not_ones_w, 1);
}

// ---------------------------------------------------------------------------
// FAST forward (mask all ones): linear-space recurrence, register-blocked.
//   u_t[j] = (sum_i u_{t-1}[i] * E[i][j]) * exp(emit_t[j]) / c_t,  c_t = u_{t-1}[0]
// CTA = 384 threads = FOUR independent 96-thread subs (one chain each) with
// per-sub named barriers. Each SMSP hosts 3 warps from 3 DIFFERENT subs; the
// subs are PHASE-STAGGERED at entry (~230 cyc apart via a dependent-FMA spin)
// so their compute bursts and latency windows (LDS 29 / SHFL 26 / bar) tile
// each other on the shared SMSP instead of colliding in lockstep.
// Per sub: thread (j = ts>>1, h = ts&1) computes TWO states {j, j+48}, half h
// of each dot: every LDS.128 of u feeds 4 FFMA2. After the shfl-combine, lane
// h finishes state j+48h. log(c_t) deferred to a post-loop reduction.
__global__ void __launch_bounds__(384, 1) crf_forward_fast_kernel(
    const float* __restrict__ emissions,
    const float* __restrict__ start_t,
    const float* __restrict__ end_t,
    const float* __restrict__ trans)
{
    const int allones = g_mask_byte ? !g_not_ones_b : !g_not_ones_w;
    if (!allones) return;

    const int tid = threadIdx.x;
    const int sub = tid / 96;          // 0..3
    const int ts  = tid - sub * 96;    // 0..95
    const int j   = ts >> 1;           // 0..47
    const int h   = ts & 1;            // dot half / owned-state selector
    const int jh  = j + 48 * h;        // owned state
    const int b   = blockIdx.x * 4 + sub;

    __shared__ __align__(16) float sh_u[4][2][C];   // [sub][buf][state]
    __shared__ float sh_hist[4][T];
    __shared__ float sh_re[4][3];
    __shared__ float sh_rl[4][3];

    // E rows [48h, 48h+48) of columns j and j+48, packed f32x2 (48 u64 regs)
    unsigned long long EJ[24], EK[24];
    {
        const float* tbJ = trans + (size_t)(48 * h) * C + j;
        const float* tbK = tbJ + 48;
#pragma unroll
        for (int k = 0; k < 24; k++) {
            EJ[k] = pack2(__expf(tbJ[(2 * k) * C]), __expf(tbJ[(2 * k + 1) * C]));
            EK[k] = pack2(__expf(tbK[(2 * k) * C]), __expf(tbK[(2 * k + 1) * C]));
        }
    }

    const float* em0 = emissions + (size_t)b * T * C;     // chain base
    const float* emS = em0 + jh;                          // owned state stream
    const float  a00 = start_t[0] + em0[0];

    sh_u[sub][0][ts] = __expf(start_t[ts] + em0[ts] - a00);   // u0 (u0[0] = 1)

    float ee1 = __expf(emS[C]);             // exp(emit) for t=1, owned state
    float er2 = emS[2 * (size_t)C];         // raw emit for t=2
    const float* em_pre = emS + 3 * (size_t)C;

    // --- phase stagger: sub k idles ~k*230 cycles on a dependent FMA chain ---
    {
        float d = 1.0f + (float)ts * 1e-7f;
        const int spin = sub * 56;               // 56 * ~4 cyc ≈ 225 cyc per sub
        for (int i = 0; i < spin; i++)
            d = fmaf(d, 1.0000001f, 1e-30f);
        if (d == 12345.678f) sh_hist[sub][0] = d;   // never true; keeps the chain
    }

    bar_sub(sub + 1);

    int buf = 0;
#pragma unroll 2
    for (int t = 1; t < T; t++) {
        const float c   = sh_u[sub][buf][0];    // broadcast LDS.32
        const float inv = frcp_fast(c);         // overlaps the dot
        if (ts == 0) sh_hist[sub][t] = c;

        // half-dots for BOTH owned states: 12 LDS.128 -> 48 FFMA2
        const ulonglong2* p2 = (const ulonglong2*)(sh_u[sub][buf] + 48 * h);
        unsigned long long aJ0 = 0ull, aJ1 = 0ull, aK0 = 0ull, aK1 = 0ull;
#pragma unroll
        for (int k = 0; k < 12; k++) {
            const ulonglong2 v = p2[k];
            aJ0 = ffma2(v.x, EJ[2 * k + 0], aJ0);
            aK0 = ffma2(v.x, EK[2 * k + 0], aK0);
            aJ1 = ffma2(v.y, EJ[2 * k + 1], aJ1);
            aK1 = ffma2(v.y, EK[2 * k + 1], aK1);
        }
        float jl, jhf, kl, khf;
        unpack2(fadd2(aJ0, aJ1), jl, jhf);
        unpack2(fadd2(aK0, aK1), kl, khf);
        float dJ = jl + jhf;                              // state j, half h
        float dK = kl + khf;                              // state j+48, half h
        dJ += __shfl_xor_sync(0xffffffffu, dJ, 1);        // full dots (both lanes)
        dK += __shfl_xor_sync(0xffffffffu, dK, 1);

        const float dot_self = h ? dK : dJ;
        sh_u[sub][buf ^ 1][jh] = dot_self * (ee1 * inv);

        // rotate owned-state emission prefetch (off critical path)
        ee1 = __expf(er2);
        if (t + 2 < T) er2 = *em_pre;
        em_pre += C;

        buf ^= 1;
        bar_sub(sub + 1);
    }

    // log_den[b] = a00 + sum_t log(c_t) + log( sum_j u_T[j] * exp(end[j]) )
    float pe = sh_u[sub][buf][jh] * __expf(end_t[jh]);    // each state once
    float pl = 0.0f;
    for (int tt = 1 + ts; tt < T; tt += 96) pl += __logf(sh_hist[sub][tt]);
#pragma unroll
    for (int off = 16; off > 0; off >>= 1) {
        pe += __shfl_xor_sync(0xffffffffu, pe, off);
        pl += __shfl_xor_sync(0xffffffffu, pl, off);
    }
    const int w    = ts >> 5;
    const int lane = ts & 31;
    if (lane == 0) { sh_re[sub][w] = pe; sh_rl[sub][w] = pl; }
    bar_sub(sub + 1);
    if (ts == 0) {
        const float te = sh_re[sub][0] + sh_re[sub][1] + sh_re[sub][2];
        const float tl = sh_rl[sub][0] + sh_rl[sub][1] + sh_rl[sub][2];
        g_den[b] = a00 + tl + __logf(te);
    }
}

// ---------------------------------------------------------------------------
// FALLBACK forward (general mask): log-space, shifted lse.
__global__ void __launch_bounds__(384, 1) crf_forward_gen_kernel(
    const float* __restrict__ emissions,
    const unsigned char* __restrict__ mask,
    const float* __restrict__ start_t,
    const float* __restrict__ end_t,
    const float* __restrict__ trans)
{
    const int allones = g_mask_byte ? !g_not_ones_b : !g_not_ones_w;
    if (allones) return;

    const int tid  = threadIdx.x;
    const int sub  = tid / C;
    const int j    = tid - sub * C;
    const int wsub = j >> 5;
    const int lane = j & 31;
    const int b    = blockIdx.x * 4 + sub;
    const int ms   = g_mask_byte ? 1 : 4;

    __shared__ __align__(16) float sh_p[2][4][C];
    __shared__ float sh_m[2][4];
    __shared__ float sh_r[4][4];

    unsigned long long E2[C / 2];
    {
        const float* tb = trans + j;
#pragma unroll
        for (int k = 0; k < C / 2; k++)
            E2[k] = pack2(__expf(tb[(2 * k) * C]), __expf(tb[(2 * k + 1) * C]));
    }

    const float* em = emissions + (size_t)b * T * C + j;
    const unsigned char* mk = mask + (size_t)b * T * ms;

    float alpha = start_t[j] + em[0];
    float m = start_t[0] + emissions[(size_t)b * T * C];

    float e1 = em[C];
    float e2 = em[2 * (size_t)C];
    unsigned char k1 = mk[1 * ms];
    unsigned char k2 = mk[2 * ms];

    int buf = 0;
    for (int t = 1; t < T; t++, buf ^= 1) {
        sh_p[buf][sub][j] = __expf(alpha - m);
        if (j == 0) sh_m[buf][sub] = alpha;
        __syncthreads();

        const ulonglong2* p2 = (const ulonglong2*)sh_p[buf][sub];
        unsigned long long a0 = 0ull, a1 = 0ull;
#pragma unroll
        for (int i = 0; i < C / 4; i++) {
            const ulonglong2 v = p2[i];
            a0 = ffma2(v.x, E2[2 * i + 0], a0);
            a1 = ffma2(v.y, E2[2 * i + 1], a1);
        }
        float lo, hi;
        unpack2(fadd2(a0, a1), lo, hi);
        const float acc = lo + hi;

        const float e_cur = e1;
        const unsigned char mc = k1;
        e1 = e2; k1 = k2;
        if (t + 2 < T) { e2 = em[(size_t)(t + 2) * C]; k2 = mk[(size_t)(t + 2) * ms]; }

        const float na = e_cur + m + __logf(acc);
        alpha = mc ? na : alpha;
        m = sh_m[buf][sub];
    }

    const float v = alpha + end_t[j];
    float wm = v;
    wm = fmaxf(wm, __shfl_xor_sync(0xffffffffu, wm, 16));
    wm = fmaxf(wm, __shfl_xor_sync(0xffffffffu, wm, 8));
    wm = fmaxf(wm, __shfl_xor_sync(0xffffffffu, wm, 4));
    wm = fmaxf(wm, __shfl_xor_sync(0xffffffffu, wm, 2));
    wm = fmaxf(wm, __shfl_xor_sync(0xffffffffu, wm, 1));
    if (lane == 0) sh_r[sub][wsub] = wm;
    __syncthreads();
    const float mf = fmaxf(fmaxf(sh_r[sub][0], sh_r[sub][1]), sh_r[sub][2]);
    __syncthreads();

    float pv = __expf(v - mf);
    pv += __shfl_xor_sync(0xffffffffu, pv, 16);
    pv += __shfl_xor_sync(0xffffffffu, pv, 8);
    pv += __shfl_xor_sync(0xffffffffu, pv, 4);
    pv += __shfl_xor_sync(0xffffffffu, pv, 2);
    pv += __shfl_xor_sync(0xffffffffu, pv, 1);
    if (lane == 0) sh_r[sub][wsub] = pv;
    __syncthreads();
    if (j == 0)
        g_den[b] = mf + __logf(sh_r[sub][0] + sh_r[sub][1] + sh_r[sub][2]);
}

// ---------------------------------------------------------------------------
// Numerator (path score): one CTA per batch element.
__global__ void __launch_bounds__(128) crf_score_kernel(
    const float* __restrict__ emissions,
    const void* __restrict__ tags_raw,
    const unsigned char* __restrict__ mask,
    const float* __restrict__ start_t,
    const float* __restrict__ end_t,
    const float* __restrict__ trans)
{
    const int b = blockIdx.x;
    const int tid = threadIdx.x;
    const int is32 = g_tag_any;
    const int ms = g_mask_byte ? 1 : 4;

    const int* tg32 = (const int*)tags_raw + (size_t)b * T;
    const long long* tg64 = (const long long*)tags_raw + (size_t)b * T;
    const unsigned char* mk = mask + (size_t)b * T * ms;
    const float* eb = emissions + (size_t)b * T * C;

    float sacc = 0.f;
    int len = 0;
    for (int t = tid; t < T; t += 128) {
        const int mt = mk[(size_t)t * ms] ? 1 : 0;
        len += mt;
        if (t >= 1 && mt) {
            const int ct = is32 ? tg32[t] : (int)tg64[t];
            const int pt = is32 ? tg32[t - 1] : (int)tg64[t - 1];
            sacc += eb[(size_t)t * C + ct] + trans[pt * C + ct];
        }
    }

    __shared__ float rs[128];
    __shared__ int   rl[128];
    rs[tid] = sacc;
    rl[tid] = len;
    __syncthreads();
#pragma unroll
    for (int off = 64; off > 0; off >>= 1) {
        if (tid < off) { rs[tid] += rs[tid + off]; rl[tid] += rl[tid + off]; }
        __syncthreads();
    }
    if (tid == 0) {
        const int t0    = is32 ? tg32[0] : (int)tg64[0];
        const int tlast = is32 ? tg32[rl[0] - 1] : (int)tg64[rl[0] - 1];
        g_num[b] = rs[0] + start_t[t0] + eb[t0] + end_t[tlast];
    }
}

// Mean over batch of (log_den - log_num).
__global__ void __launch_bounds__(512) crf_final_kernel(float* __restrict__ out)
{
    const int tid = threadIdx.x;
    __shared__ float r[512];
    r[tid] = g_den[tid] - g_num[tid];
    __syncthreads();
#pragma unroll
    for (int off = 256; off > 0; off >>= 1) {
        if (tid < off) r[tid] += r[tid + off];
        __syncthreads();
    }
    if (tid == 0) out[0] = r[0] * (1.0f / (float)B);
}

extern "C" void kernel_launch(void* const* d_in, const int* in_sizes, int n_in,
                              void* d_out, int out_size)
{
    const float*         emissions = (const float*)d_in[0];
    const void*          tags      = d_in[1];
    const unsigned char* mask      = (const unsigned char*)d_in[2];
    const float*         start_t   = (const float*)d_in[3];
    const float*         end_t     = (const float*)d_in[4];
    const float*         trans     = (const float*)d_in[5];
    float* out = (float*)d_out;

    crf_init_kernel<<<1, 1>>>();
    crf_detect_a_kernel<<<64, 256>>>((const int*)tags, (const unsigned int*)mask);
    crf_detect_b_kernel<<<64, 256>>>((const unsigned int*)mask);
    crf_forward_fast_kernel<<<B / 4, 384>>>(emissions, start_t, end_t, trans);
    crf_forward_gen_kernel<<<B / 4, 384>>>(emissions, mask, start_t, end_t, trans);
    crf_score_kernel<<<B, 128>>>(emissions, tags, mask, start_t, end_t, trans);
    crf_final_kernel<<<1, 512>>>(out);
}